// round 16
// baseline (speedup 1.0000x reference)
#include <cuda_runtime.h>
#include <cstdint>

#define NITEMS 4096
#define TPB    512
#define NWARP  16
#define CAP    600.0f
#define MU     1e-3f
#define MAXIT  16
#define LAM0   0.82f       // ensemble warm start (integral estimate lam* ~ 0.83)
#define PHI_EMIT 0.15f     // exit gate; 2nd-order emit absorbs dlam up to ~4e-4
#define GRID_P 304         // persistent grid: 2 CTAs/SM x 152 SMs

typedef unsigned long long u64p;   // packed f32x2

__device__ __forceinline__ float frcp(float v) {
    float r;
    asm("rcp.approx.ftz.f32 %0, %1;" : "=f"(r) : "f"(v));
    return r;
}
__device__ __forceinline__ float frsq(float v) {
    float r;
    asm("rsqrt.approx.ftz.f32 %0, %1;" : "=f"(r) : "f"(v));
    return r;
}
__device__ __forceinline__ u64p pack2(float lo, float hi) {
    u64p r;
    asm("mov.b64 %0, {%1, %2};" : "=l"(r) : "f"(lo), "f"(hi));
    return r;
}
__device__ __forceinline__ void unpack2(u64p v, float& lo, float& hi) {
    asm("mov.b64 {%0, %1}, %2;" : "=f"(lo), "=f"(hi) : "l"(v));
}
__device__ __forceinline__ uint32_t smem_u32(const void* p) {
    uint32_t a;
    asm("{ .reg .u64 t; cvta.to.shared.u64 t, %1; cvt.u32.u64 %0, t; }"
        : "=r"(a) : "l"(p));
    return a;
}
#define CP_ASYNC16(dst, src) \
    asm volatile("cp.async.cg.shared.global [%0], [%1], 16;" :: "r"(dst), "l"(src))
#define CP_COMMIT() asm volatile("cp.async.commit_group;" ::: "memory")
#define CP_WAIT0()  asm volatile("cp.async.wait_group 0;" ::: "memory")

__device__ __forceinline__ float wsum32(float v) {
#pragma unroll
    for (int o = 16; o > 0; o >>= 1) v += __shfl_xor_sync(0xffffffffu, v, o);
    return v;
}
// reduce 16 per-warp partials duplicated across the warp (idx = lane&15)
__device__ __forceinline__ float bsum16(float v) {
#pragma unroll
    for (int o = 8; o > 0; o >>= 1) v += __shfl_xor_sync(0xffffffffu, v, o);
    return v;
}

// interior root of g x^2 - (g+2mu) x + mu = 0, cancellation-free:
//   t(a) = 2mu / (a + 2mu + sqrt(a^2+4mu^2)),  a = |g|;  x = g>=0 ? t : 1-t
// nd = -dx/dg = t * rden * (1 + a/D) = 1/H  (same value for both signs)
__device__ __forceinline__ void xofg(float g, float& x, float& nd) {
    const float a    = fabsf(g);
    const float u    = fmaf(a, a, 4.0f * MU * MU);
    const float rD   = frsq(u);
    const float den  = fmaf(u, rD, a + 2.0f * MU);   // a + 2mu + sqrt(u)
    const float rden = frcp(den);
    const float t    = (2.0f * MU) * rden;
    x  = (g >= 0.0f) ? t : 1.0f - t;
    nd = (t * rden) * fmaf(a, rD, 1.0f);
}

// one elementwise evaluation quad at lam, accumulating s1/s2 and stashing x, nd
#define EVAL_QUAD(cf, wf, base)                                              \
    do {                                                                     \
        float x0, x1, x2, x3, n0, n1, n2, n3;                                \
        xofg(fmaf(lam, wf.x, -cf.x), x0, n0);                                \
        s1 = fmaf(wf.x, x0, s1); s2 = fmaf(wf.x * wf.x, n0, s2);             \
        xofg(fmaf(lam, wf.y, -cf.y), x1, n1);                                \
        s1 = fmaf(wf.y, x1, s1); s2 = fmaf(wf.y * wf.y, n1, s2);             \
        xofg(fmaf(lam, wf.z, -cf.z), x2, n2);                                \
        s1 = fmaf(wf.z, x2, s1); s2 = fmaf(wf.z * wf.z, n2, s2);             \
        xofg(fmaf(lam, wf.w, -cf.w), x3, n3);                                \
        s1 = fmaf(wf.w, x3, s1); s2 = fmaf(wf.w * wf.w, n3, s2);             \
        xP[base]      = pack2(x0, x1);                                       \
        xP[base + 1]  = pack2(x2, x3);                                       \
        ndP[base]     = pack2(n0, n1);                                       \
        ndP[base + 1] = pack2(n2, n3);                                       \
    } while (0)

// second-order emit for one element:
//   out = x - (w*dlam)*nd + 0.5*(w*dlam)^2*x''
//   x'' = 2*nd*(t1 - g*nd)/Fx,  t1 = 2x-1,  Fx = g*t1 - 2mu  (|Fx| >= 2mu)
__device__ __forceinline__ float emit_one(float x, float nd, float w,
                                          float c, float lam, float dlam) {
    const float g   = fmaf(lam, w, -c);
    const float wd  = w * dlam;
    const float t1  = fmaf(2.0f, x, -1.0f);
    const float Fx  = fmaf(g, t1, -2.0f * MU);
    const float num = 2.0f * nd * fmaf(-g, nd, t1);
    const float xpp = num * frcp(Fx);
    const float o1  = fmaf(-wd, nd, x);
    return fmaf(0.5f * wd * wd, xpp, o1);
}

__global__ void __launch_bounds__(TPB, 2)
ipm_kernel(const float* __restrict__ costs,
           const float* __restrict__ wglob,
           float* __restrict__ out, int nrows)
{
    __shared__ float4 sc[4 * TPB];          // two 16KB cost-row buffers
    __shared__ float sR[2][2][NWARP];       // [parity][s1|s2][warp]

    const int tid = threadIdx.x, lane = tid & 31, wid = tid >> 5;
    const uint32_t sc_u32 = smem_u32(sc);

    // weights: load once per CTA, resident in registers
    const float4 wf0 = ((const float4*)wglob)[tid];
    const float4 wf1 = ((const float4*)wglob)[TPB + tid];

    // prefetch first row into buffer 0 (zero-register GMEM->SMEM)
    {
        const int r0 = (blockIdx.x < nrows) ? blockIdx.x : 0;
        const float4* src = (const float4*)(costs + (size_t)r0 * NITEMS);
        CP_ASYNC16(sc_u32 + tid * 16, src + tid);
        CP_ASYNC16(sc_u32 + (TPB + tid) * 16, src + TPB + tid);
        CP_COMMIT();
    }

    int buf = 0;
#pragma unroll 1
    for (int r = blockIdx.x; r < nrows; r += GRID_P) {
        CP_WAIT0();
        __syncthreads();   // row data visible; fences sc/sR reuse across rows

        // prefetch the NEXT row into the other buffer; completes during solve
        {
            const int rn = r + GRID_P;
            const float4* src =
                (const float4*)(costs + (size_t)(rn < nrows ? rn : r) * NITEMS);
            const uint32_t d = sc_u32 + (buf ^ 1) * (2 * TPB * 16);
            CP_ASYNC16(d + tid * 16, src + tid);
            CP_ASYNC16(d + (TPB + tid) * 16, src + TPB + tid);
            CP_COMMIT();
        }

        const float4* scb = sc + buf * (2 * TPB);

        // ---- bracketed Newton on lambda (identical math to R14) ------------
        float lam = LAM0, lo = -30.0f, hi = 30.0f, dlam = 0.0f;
        u64p xP[4], ndP[4];
        float s1 = 0.0f, s2 = 0.0f;
        {
            const float4 cf0 = scb[tid], cf1 = scb[TPB + tid];
            EVAL_QUAD(cf0, wf0, 0);
            EVAL_QUAD(cf1, wf1, 2);
        }
#pragma unroll 1
        for (int it = 0; it < MAXIT; ++it) {
            float r1 = wsum32(s1), r2 = wsum32(s2);
            const int par = it & 1;
            if (lane == 0) { sR[par][0][wid] = r1; sR[par][1][wid] = r2; }
            __syncthreads();
            r1 = bsum16(sR[par][0][lane & 15]);     // identical in all threads
            r2 = bsum16(sR[par][1][lane & 15]);

            const float phi  = r1 - CAP;
            const float step = phi * frcp(r2);      // Newton increment
            if (fabsf(phi) < PHI_EMIT || it == MAXIT - 1) {
                dlam = step;                        // applied at emit (2nd order)
                break;                              // xP/ndP match current lam
            }
            if (phi > 0.0f) lo = lam; else hi = lam;   // phi monotone decreasing
            float ln = lam + step;
            if (!(ln > lo && ln < hi)) ln = 0.5f * (lo + hi);
            lam = ln;

            s1 = 0.0f; s2 = 0.0f;
            const float4 cf0 = scb[tid], cf1 = scb[TPB + tid];
            EVAL_QUAD(cf0, wf0, 0);
            EVAL_QUAD(cf1, wf1, 2);
        }

        // ---- emit: out = x - dlam*w*nd + 0.5*(dlam*w)^2*x''  ---------------
        {
            const float4 cf0 = scb[tid], cf1 = scb[TPB + tid];
            float4* orow = (float4*)(out + (size_t)r * NITEMS);
            float x0, x1, x2, x3, n0, n1, n2, n3;
            float4 o;
            unpack2(xP[0], x0, x1);  unpack2(xP[1], x2, x3);
            unpack2(ndP[0], n0, n1); unpack2(ndP[1], n2, n3);
            o.x = emit_one(x0, n0, wf0.x, cf0.x, lam, dlam);
            o.y = emit_one(x1, n1, wf0.y, cf0.y, lam, dlam);
            o.z = emit_one(x2, n2, wf0.z, cf0.z, lam, dlam);
            o.w = emit_one(x3, n3, wf0.w, cf0.w, lam, dlam);
            orow[tid] = o;
            unpack2(xP[2], x0, x1);  unpack2(xP[3], x2, x3);
            unpack2(ndP[2], n0, n1); unpack2(ndP[3], n2, n3);
            o.x = emit_one(x0, n0, wf1.x, cf1.x, lam, dlam);
            o.y = emit_one(x1, n1, wf1.y, cf1.y, lam, dlam);
            o.z = emit_one(x2, n2, wf1.z, cf1.z, lam, dlam);
            o.w = emit_one(x3, n3, wf1.w, cf1.w, lam, dlam);
            orow[TPB + tid] = o;
        }

        buf ^= 1;
    }
}

extern "C" void kernel_launch(void* const* d_in, const int* in_sizes, int n_in,
                              void* d_out, int out_size)
{
    const float* costs = (const float*)d_in[0];
    const float* wv    = (const float*)d_in[1];
    int costs_elems = in_sizes[0];
    if (n_in >= 2 && in_sizes[0] == NITEMS && in_sizes[1] > NITEMS) {
        costs = (const float*)d_in[1];
        wv    = (const float*)d_in[0];
        costs_elems = in_sizes[1];
    }
    const int B = costs_elems / NITEMS;
    const int grid = (B < GRID_P) ? B : GRID_P;
    ipm_kernel<<<grid, TPB>>>(costs, wv, (float*)d_out, B);
}

// round 17
// speedup vs baseline: 1.7066x; 1.7066x over previous
#include <cuda_runtime.h>
#include <cstdint>

#define NITEMS 4096
#define TPB    512
#define NWARP  16
#define EPT    8
#define CAP    600.0f
#define MU     1e-3f
#define MAXIT  16
#define LAM0   0.82f       // ensemble warm start (integral estimate lam* ~ 0.83)
#define PHI_EMIT 0.15f     // exit gate (validated in R14); emit recomputes exactly

__device__ __forceinline__ float frcp(float v) {
    float r;
    asm("rcp.approx.ftz.f32 %0, %1;" : "=f"(r) : "f"(v));
    return r;
}
__device__ __forceinline__ float frsq(float v) {
    float r;
    asm("rsqrt.approx.ftz.f32 %0, %1;" : "=f"(r) : "f"(v));
    return r;
}

__device__ __forceinline__ float wsum32(float v) {
#pragma unroll
    for (int o = 16; o > 0; o >>= 1) v += __shfl_xor_sync(0xffffffffu, v, o);
    return v;
}
// reduce 16 per-warp partials duplicated across the warp (idx = lane&15)
__device__ __forceinline__ float bsum16(float v) {
#pragma unroll
    for (int o = 8; o > 0; o >>= 1) v += __shfl_xor_sync(0xffffffffu, v, o);
    return v;
}

// interior root of g x^2 - (g+2mu) x + mu = 0, cancellation-free:
//   t = 2mu / den, den = |g| + 2mu + sqrt(g^2+4mu^2);  x = g>=0 ? t : 1-t
// nd = -dx/dg = (t*rden)*(1 + |g|/D) = 1/H   (same value for both signs)
__device__ __forceinline__ void xofg(float g, float& x, float& nd) {
    const float a    = fabsf(g);
    const float u    = fmaf(g, g, 4.0f * MU * MU);
    const float rD   = frsq(u);
    const float den  = fmaf(u, rD, a + 2.0f * MU);
    const float rden = frcp(den);
    const float t    = (2.0f * MU) * rden;
    x  = (g >= 0.0f) ? t : 1.0f - t;
    nd = (t * rden) * fmaf(a, rD, 1.0f);
}

// x only (for the exact emit recompute — no derivative needed)
__device__ __forceinline__ float xonly(float g) {
    const float a   = fabsf(g);
    const float u   = fmaf(g, g, 4.0f * MU * MU);
    const float rD  = frsq(u);
    const float den = fmaf(u, rD, a + 2.0f * MU);
    const float t   = (2.0f * MU) * frcp(den);
    return (g >= 0.0f) ? t : 1.0f - t;
}

__global__ void __launch_bounds__(TPB, 2)
ipm_kernel(const float* __restrict__ costs,
           const float* __restrict__ wglob,
           float* __restrict__ out)
{
    __shared__ float sR[2][2][NWARP];       // [parity][s1|s2][warp]

    const int tid = threadIdx.x, lane = tid & 31, wid = tid >> 5;

    // ---- everything register-resident: c, w, w^2 (24 regs of arrays) -------
    float cA[EPT], wA[EPT], w2A[EPT];
    float lam = LAM0, lo = -30.0f, hi = 30.0f;
    float s1 = 0.0f, s2 = 0.0f;

    {
        const float4* cg = (const float4*)(costs + (size_t)blockIdx.x * NITEMS);
        const float4* wg = (const float4*)wglob;
        const float4 c0 = cg[tid], c1 = cg[TPB + tid];
        const float4 w0 = wg[tid], w1 = wg[TPB + tid];
        cA[0] = c0.x; cA[1] = c0.y; cA[2] = c0.z; cA[3] = c0.w;
        cA[4] = c1.x; cA[5] = c1.y; cA[6] = c1.z; cA[7] = c1.w;
        wA[0] = w0.x; wA[1] = w0.y; wA[2] = w0.z; wA[3] = w0.w;
        wA[4] = w1.x; wA[5] = w1.y; wA[6] = w1.z; wA[7] = w1.w;
#pragma unroll
        for (int i = 0; i < EPT; i++) w2A[i] = wA[i] * wA[i];
        // fused first evaluation at LAM0
#pragma unroll
        for (int i = 0; i < EPT; i++) {
            float x, nd;
            xofg(fmaf(lam, wA[i], -cA[i]), x, nd);
            s1 = fmaf(wA[i], x, s1);
            s2 = fmaf(w2A[i], nd, s2);
        }
    }

    // ---- 1-D safeguarded (bracketed) Newton on lambda ----------------------
    //   phi(lam) = sum w*x(lam) - CAP,  phi' = -s2
    // Exit at |phi| < PHI_EMIT with the pending Newton step applied to lam;
    // the emit recomputes x(lam_final) exactly (no Taylor, no stash).
    float lamf = lam;
#pragma unroll 1
    for (int it = 0; it < MAXIT; ++it) {
        float r1 = wsum32(s1), r2 = wsum32(s2);
        const int par = it & 1;
        if (lane == 0) { sR[par][0][wid] = r1; sR[par][1][wid] = r2; }
        __syncthreads();
        r1 = bsum16(sR[par][0][lane & 15]);     // identical in all threads
        r2 = bsum16(sR[par][1][lane & 15]);

        const float phi  = r1 - CAP;
        const float step = phi * frcp(r2);      // Newton increment
        if (fabsf(phi) < PHI_EMIT || it == MAXIT - 1) {
            lamf = lam + step;                  // final lambda for exact emit
            break;
        }
        if (phi > 0.0f) lo = lam; else hi = lam;   // phi monotone decreasing
        float ln = lam + step;
        if (!(ln > lo && ln < hi)) ln = 0.5f * (lo + hi);
        lam = ln;

        // next evaluation: everything from registers
        s1 = 0.0f; s2 = 0.0f;
#pragma unroll
        for (int i = 0; i < EPT; i++) {
            float x, nd;
            xofg(fmaf(lam, wA[i], -cA[i]), x, nd);
            s1 = fmaf(wA[i], x, s1);
            s2 = fmaf(w2A[i], nd, s2);
        }
    }

    // ---- emit: out = x(lam_final), exact closed form ------------------------
    {
        float r[EPT];
#pragma unroll
        for (int i = 0; i < EPT; i++)
            r[i] = xonly(fmaf(lamf, wA[i], -cA[i]));
        float4* orow = (float4*)(out + (size_t)blockIdx.x * NITEMS);
        float4 o;
        o.x = r[0]; o.y = r[1]; o.z = r[2]; o.w = r[3];
        orow[tid] = o;
        o.x = r[4]; o.y = r[5]; o.z = r[6]; o.w = r[7];
        orow[TPB + tid] = o;
    }
}

extern "C" void kernel_launch(void* const* d_in, const int* in_sizes, int n_in,
                              void* d_out, int out_size)
{
    const float* costs = (const float*)d_in[0];
    const float* wv    = (const float*)d_in[1];
    int costs_elems = in_sizes[0];
    if (n_in >= 2 && in_sizes[0] == NITEMS && in_sizes[1] > NITEMS) {
        costs = (const float*)d_in[1];
        wv    = (const float*)d_in[0];
        costs_elems = in_sizes[1];
    }
    const int B = costs_elems / NITEMS;
    ipm_kernel<<<B, TPB>>>(costs, wv, (float*)d_out);
}